// round 9
// baseline (speedup 1.0000x reference)
#include <cuda_runtime.h>
#include <cuda_fp16.h>
#include <cstdint>

#define C   128
#define NN  50000
#define NE  600000
#define NB  49          // ceil(NN/1024)

// ---------------- device scratch (no allocations allowed) ----------------
__device__ __align__(16) __half g_x0f[2 * NN * C];        // fp16 layer-0 inputs
__device__ __align__(16) __half g_x1f[2 * NN * C];        // fp16 layer-0 outputs
__device__ __align__(16) __half g_Wuf[2][C * 384];
__device__ __align__(16) __half g_Wif[2][C * 256];
__device__ float g_b[2][2 * C];
__device__ int   g_deg[3 * NN];
__device__ int   g_rowptr[3 * (NN + 1)];
__device__ int   g_cursor[3 * NN];
__device__ int   g_srcs[3 * NE];
__device__ int   g_bsum[3 * 64];
__device__ int   g_bofs[3 * 64];

// ---------------- CSR build ----------------
__global__ void histo3(const int* __restrict__ e0, const int* __restrict__ e1, const int* __restrict__ e2,
                       int* __restrict__ deg) {
    int z = blockIdx.y;
    const int* dst = (z == 0 ? e0 : (z == 1 ? e1 : e2)) + NE;
    int* dg = deg + z * NN;
    for (int i = blockIdx.x * blockDim.x + threadIdx.x; i < NE; i += gridDim.x * blockDim.x)
        atomicAdd(&dg[dst[i]], 1);
}

__global__ void scan_partial(const int* __restrict__ deg, int* __restrict__ bsum) {
    int z = blockIdx.y, b = blockIdx.x, t = threadIdx.x;
    int lane = t & 31, wid = t >> 5;
    int s = 0;
#pragma unroll
    for (int q = 0; q < 4; q++) {
        int i = b * 1024 + q * 256 + t;
        if (i < NN) s += deg[z * NN + i];
    }
    for (int o = 16; o; o >>= 1) s += __shfl_down_sync(0xffffffffu, s, o);
    __shared__ int ws[8];
    if (lane == 0) ws[wid] = s;
    __syncthreads();
    if (t == 0) {
        int tot = 0;
#pragma unroll
        for (int w = 0; w < 8; w++) tot += ws[w];
        bsum[z * 64 + b] = tot;
    }
}

__global__ void scan_bsum(const int* __restrict__ bsum, int* __restrict__ bofs) {
    int t = threadIdx.x;
    int z = t >> 5, lane = t & 31;
    if (z < 3) {
        int carry = 0;
        for (int bb = 0; bb < 64; bb += 32) {
            int idx = bb + lane;
            int v = (idx < NB) ? bsum[z * 64 + idx] : 0;
            int incl = v;
            for (int o = 1; o < 32; o <<= 1) {
                int x = __shfl_up_sync(0xffffffffu, incl, o);
                if (lane >= o) incl += x;
            }
            bofs[z * 64 + idx] = carry + incl - v;
            carry += __shfl_sync(0xffffffffu, incl, 31);
        }
    }
}

__global__ void scan_final(const int* __restrict__ deg, const int* __restrict__ bofs,
                           int* __restrict__ rowptr, int* __restrict__ cursor) {
    int z = blockIdx.y, b = blockIdx.x, t = threadIdx.x;
    int lane = t & 31, wid = t >> 5;
    int base = b * 1024 + t * 4;
    int v[4]; int tsum = 0;
#pragma unroll
    for (int q = 0; q < 4; q++) {
        int i = base + q;
        v[q] = (i < NN) ? deg[z * NN + i] : 0;
        tsum += v[q];
    }
    int incl = tsum;
    for (int o = 1; o < 32; o <<= 1) {
        int x = __shfl_up_sync(0xffffffffu, incl, o);
        if (lane >= o) incl += x;
    }
    __shared__ int ws[8];
    if (lane == 31) ws[wid] = incl;
    __syncthreads();
    int wofs = 0;
#pragma unroll
    for (int w = 0; w < 8; w++) wofs += (w < wid) ? ws[w] : 0;
    int run = bofs[z * 64 + b] + wofs + incl - tsum;
#pragma unroll
    for (int q = 0; q < 4; q++) {
        int i = base + q;
        if (i < NN) {
            rowptr[z * (NN + 1) + i] = run;
            cursor[z * NN + i] = run;
            if (i == NN - 1) rowptr[z * (NN + 1) + NN] = run + v[q];
            run += v[q];
        }
    }
}

__global__ void fillcsr3(const int* __restrict__ e0, const int* __restrict__ e1, const int* __restrict__ e2,
                         int* __restrict__ cursor, int* __restrict__ srcs) {
    int z = blockIdx.y;
    const int* base = (z == 0 ? e0 : (z == 1 ? e1 : e2));
    const int* src = base;
    const int* dst = base + NE;
    int* cur = cursor + z * NN;
    int* out = srcs + z * NE;
    for (int i = blockIdx.x * blockDim.x + threadIdx.x; i < NE; i += gridDim.x * blockDim.x) {
        int p = atomicAdd(&cur[dst[i]], 1);
        out[p] = src[i];
    }
}

// ---------------- fp16 conversion of inputs ----------------
__global__ void split_x(const float* __restrict__ xu, const float* __restrict__ xi,
                        __half* __restrict__ xf) {
    const size_t NC = (size_t)NN * C;
    int y = blockIdx.y;
    const float* x = y ? xi : xu;
    __half* of = xf + y * NC;
    int n4 = NC / 4;
    for (int i = blockIdx.x * blockDim.x + threadIdx.x; i < n4; i += gridDim.x * blockDim.x) {
        float4 v = ((const float4*)x)[i];
        __half2 f0 = __floats2half2_rn(v.x, v.y);
        __half2 f1 = __floats2half2_rn(v.z, v.w);
        uint2 fp; fp.x = *(uint32_t*)&f0; fp.y = *(uint32_t*)&f1;
        ((uint2*)of)[i] = fp;
    }
}

// ---------------- weight prep: concat to fp16 ----------------
__global__ void prep_user(const float* __restrict__ Wl_iu, const float* __restrict__ b_iu, const float* __restrict__ Wr_iu,
                          const float* __restrict__ Wl_uu, const float* __restrict__ b_uu, const float* __restrict__ Wr_uu,
                          __half* __restrict__ Wf, float* __restrict__ bv) {
    int i = blockIdx.x * blockDim.x + threadIdx.x;
    if (i < C * 384) {
        int c = i / 384, k = i - c * 384;
        float v;
        if (k < 128)      v = Wl_iu[c * 128 + k];
        else if (k < 256) v = Wl_uu[c * 128 + k - 128];
        else              v = Wr_iu[c * 128 + k - 256] + Wr_uu[c * 128 + k - 256];
        Wf[i] = __float2half_rn(v);
        if (i < C) bv[i] = b_iu[i] + b_uu[i];
    }
}

__global__ void prep_item(const float* __restrict__ Wl_ui, const float* __restrict__ b_ui, const float* __restrict__ Wr_ui,
                          __half* __restrict__ Wf, float* __restrict__ bv) {
    int i = blockIdx.x * blockDim.x + threadIdx.x;
    if (i < C * 256) {
        int c = i / 256, k = i - c * 256;
        float v = (k < 128) ? Wl_ui[c * 128 + k] : Wr_ui[c * 128 + k - 128];
        Wf[i] = __float2half_rn(v);
        if (i < C) bv[i] = b_ui[i];
    }
}

// ---------------- helpers ----------------
__device__ __forceinline__ uint32_t smem_u32(const void* p) {
    uint32_t a;
    asm("{ .reg .u64 t; cvta.to.shared.u64 t, %1; cvt.u32.u64 %0, t; }" : "=r"(a) : "l"(p));
    return a;
}

#define LDM4(r, addr) \
    asm volatile("ldmatrix.sync.aligned.m8n8.x4.shared.b16 {%0,%1,%2,%3}, [%4];" \
        : "=r"((r)[0]), "=r"((r)[1]), "=r"((r)[2]), "=r"((r)[3]) : "r"(addr))

#define MMAF16(d, a, b0, b1) \
    asm volatile("mma.sync.aligned.m16n8k16.row.col.f32.f16.f16.f32 " \
        "{%0,%1,%2,%3},{%4,%5,%6,%7},{%8,%9},{%0,%1,%2,%3};" \
        : "+f"((d)[0]), "+f"((d)[1]), "+f"((d)[2]), "+f"((d)[3]) \
        : "r"((a)[0]), "r"((a)[1]), "r"((a)[2]), "r"((a)[3]), "r"(b0), "r"(b1))

__device__ __forceinline__ void cp16(uint32_t dst, const void* src, bool pred) {
    int sz = pred ? 16 : 0;
    asm volatile("cp.async.cg.shared.global [%0], [%1], 16, %2;" :: "r"(dst), "l"(src), "r"(sz));
}
__device__ __forceinline__ void cp_commit() { asm volatile("cp.async.commit_group;"); }
__device__ __forceinline__ void cp_wait1() { asm volatile("cp.async.wait_group 1;"); }

__device__ __forceinline__ void add8(float* acc, uint4 v) {
    __half2* p = (__half2*)&v;
#pragma unroll
    for (int i = 0; i < 4; i++) {
        float2 f = __half22float2(p[i]);
        acc[2 * i] += f.x;
        acc[2 * i + 1] += f.y;
    }
}

// ---------------- fused aggregate + GEMM + bias + LN + ReLU ----------------
// CTA = 128 nodes. Phase A: warps dynamically aggregate (NCH-1) agg-sources for
// these nodes straight into smem A-tiles (144B pitch, 64-half chunks); direct-x
// chunks + W stream in via cp.async. Phase B: double-buffered-W HMMA K-loop.
#define TILE_B 18432           // one chunk tile: 128 rows x 144B
#define YS_PITCH 136

template <int NCH>
__global__ void __launch_bounds__(256, 1)
gemm_fused(const __half* __restrict__ xg0, const int* __restrict__ rp0, const int* __restrict__ ss0,
           const __half* __restrict__ xg1, const int* __restrict__ rp1, const int* __restrict__ ss1,
           const __half* __restrict__ xdir, const __half* __restrict__ Wf,
           const float* __restrict__ bias, const float* __restrict__ lnw, const float* __restrict__ lnb,
           float* __restrict__ out, __half* __restrict__ outf, int n) {
    extern __shared__ __align__(16) char smp[];
    const int KTOT = NCH * 128;
    const int NC2 = NCH * 2;
    const int W_OFF = NC2 * TILE_B;
    const int CTRL_OFF = W_OFF + 2 * TILE_B;
    uint32_t sbase = smem_u32(smp);
    __shared__ int sctr;

    int tid = threadIdx.x, lane = tid & 31, wid = tid >> 5;
    int wr = wid >> 1, wc = wid & 1;
    int nodeBase = blockIdx.x * 128;
    int half = lane >> 4, q = lane & 15;

    float* sBias = (float*)(smp + CTRL_OFF);
    float* sLnw  = (float*)(smp + CTRL_OFF + 512);
    float* sLnb  = (float*)(smp + CTRL_OFF + 1024);

    if (tid == 0) sctr = 0;
    if (tid < 128) { sBias[tid] = bias[tid]; sLnw[tid] = lnw[tid]; sLnb[tid] = lnb[tid]; }

    auto load_W = [&](int c2, int buf) {
#pragma unroll
        for (int i = 0; i < 4; i++) {
            int j = i * 256 + tid;
            int r = j >> 3, qq = j & 7;
            cp16(sbase + W_OFF + buf * TILE_B + r * 144 + qq * 16,
                 Wf + (size_t)r * KTOT + c2 * 64 + qq * 8, true);
        }
    };

    // direct-x chunks (source NCH-1) via cp.async
#pragma unroll
    for (int i = 0; i < 8; i++) {
        int j = i * 256 + tid;                  // 2048 slots = 2 chunks x 1024
        int h = j >> 10, r = (j >> 3) & 127, qq = j & 7;
        int node = nodeBase + r;
        bool ok = node < n;
        cp16(sbase + ((NCH - 1) * 2 + h) * TILE_B + r * 144 + qq * 16,
             xdir + (size_t)(ok ? node : 0) * C + h * 64 + qq * 8, ok);
    }
    load_W(0, 0);
    cp_commit();          // G0: x chunks + W0
    __syncthreads();      // sctr + ctrl visible

    // ---- Phase A: dynamic aggregation into smem ----
    const int NAGG = NCH - 1;
    const int TASKS = NAGG * 128;
    for (;;) {
        int t;
        if (lane == 0) t = atomicAdd(&sctr, 1);
        t = __shfl_sync(0xffffffffu, t, 0);
        if (t >= TASKS) break;
        int sSel = t >> 7, row = t & 127;
        int w = nodeBase + row;
        const __half* xg = sSel ? xg1 : xg0;
        const int* rp = sSel ? rp1 : rp0;
        const int* ss = sSel ? ss1 : ss0;
        float acc[8];
#pragma unroll
        for (int i = 0; i < 8; i++) acc[i] = 0.f;
        float inv = 1.f;
        if (w < n) {
            int beg = rp[w], end = rp[w + 1];
            int e = beg;
            for (; e + 8 <= end; e += 8) {
                int s0 = ss[e + half];
                int s1 = ss[e + 2 + half];
                int s2 = ss[e + 4 + half];
                int s3 = ss[e + 6 + half];
                uint4 v0 = *(const uint4*)(xg + (size_t)s0 * C + q * 8);
                uint4 v1 = *(const uint4*)(xg + (size_t)s1 * C + q * 8);
                uint4 v2 = *(const uint4*)(xg + (size_t)s2 * C + q * 8);
                uint4 v3 = *(const uint4*)(xg + (size_t)s3 * C + q * 8);
                add8(acc, v0); add8(acc, v1); add8(acc, v2); add8(acc, v3);
            }
            for (; e + 2 <= end; e += 2) {
                int s = ss[e + half];
                uint4 v = *(const uint4*)(xg + (size_t)s * C + q * 8);
                add8(acc, v);
            }
            if (e < end && half == 0) {
                int s = ss[e];
                uint4 v = *(const uint4*)(xg + (size_t)s * C + q * 8);
                add8(acc, v);
            }
            int d = end - beg;
            inv = 1.0f / (float)(d > 1 ? d : 1);
        }
#pragma unroll
        for (int i = 0; i < 8; i++) acc[i] += __shfl_xor_sync(0xffffffffu, acc[i], 16);
        if (half == 0) {
            __half2 h0 = __floats2half2_rn(acc[0] * inv, acc[1] * inv);
            __half2 h1 = __floats2half2_rn(acc[2] * inv, acc[3] * inv);
            __half2 h2 = __floats2half2_rn(acc[4] * inv, acc[5] * inv);
            __half2 h3 = __floats2half2_rn(acc[6] * inv, acc[7] * inv);
            uint4 o;
            o.x = *(uint32_t*)&h0; o.y = *(uint32_t*)&h1;
            o.z = *(uint32_t*)&h2; o.w = *(uint32_t*)&h3;
            *(uint4*)(smp + (sSel * 2 + (q >> 3)) * TILE_B + row * 144 + (q & 7) * 16) = o;
        }
    }

    // ---- Phase B: HMMA K-loop (A in smem, W double-buffered) ----
    float D[2][8][4];
#pragma unroll
    for (int a = 0; a < 2; a++)
#pragma unroll
        for (int b = 0; b < 8; b++)
#pragma unroll
            for (int c = 0; c < 4; c++) D[a][b][c] = 0.f;

#pragma unroll
    for (int c2 = 0; c2 < NC2; c2++) {
        if (c2 + 1 < NC2) load_W(c2 + 1, (c2 + 1) & 1);
        cp_commit();
        cp_wait1();
        __syncthreads();
        uint32_t bbA = sbase + c2 * TILE_B;
        uint32_t bbW = sbase + W_OFF + (c2 & 1) * TILE_B;
#pragma unroll
        for (int s = 0; s < 4; s++) {
            uint32_t av[2][4], bv4[4][4];
#pragma unroll
            for (int mt = 0; mt < 2; mt++) {
                int row = wr * 32 + mt * 16 + (lane & 15);
                int kb = s * 32 + (lane >> 4) * 16;
                LDM4(av[mt], bbA + row * 144 + kb);
            }
#pragma unroll
            for (int bt = 0; bt < 4; bt++) {
                int rown = wc * 64 + bt * 16 + ((lane >> 4) * 8 + (lane & 7));
                int kb = s * 32 + ((lane >> 3) & 1) * 16;
                LDM4(bv4[bt], bbW + rown * 144 + kb);
            }
#pragma unroll
            for (int mt = 0; mt < 2; mt++)
#pragma unroll
                for (int bt = 0; bt < 4; bt++) {
                    MMAF16(D[mt][bt * 2],     av[mt], bv4[bt][0], bv4[bt][1]);
                    MMAF16(D[mt][bt * 2 + 1], av[mt], bv4[bt][2], bv4[bt][3]);
                }
        }
        __syncthreads();
    }

    // ---- epilogue: accum + bias -> smem, LN + ReLU, fp32/fp16 stores ----
    float* ys = (float*)smp;
#pragma unroll
    for (int mt = 0; mt < 2; mt++) {
        int r0 = wr * 32 + mt * 16 + (lane >> 2);
#pragma unroll
        for (int bt = 0; bt < 8; bt++) {
            int nn = wc * 64 + bt * 8 + (lane & 3) * 2;
            float b0 = sBias[nn], b1 = sBias[nn + 1];
            float2 v0 = {D[mt][bt][0] + b0, D[mt][bt][1] + b1};
            float2 v1 = {D[mt][bt][2] + b0, D[mt][bt][3] + b1};
            *(float2*)&ys[r0 * YS_PITCH + nn] = v0;
            *(float2*)&ys[(r0 + 8) * YS_PITCH + nn] = v1;
        }
    }
    __syncthreads();
    if (tid < 128) {
        int row = tid;
        float s = 0.f, s2 = 0.f;
#pragma unroll
        for (int c = 0; c < 128; c++) {
            float v = ys[row * YS_PITCH + c];
            s += v; s2 += v * v;
        }
        float mu = s * (1.f / 128.f);
        float rs = rsqrtf(s2 * (1.f / 128.f) - mu * mu + 1e-5f);
#pragma unroll
        for (int c = 0; c < 128; c++) {
            float y = (ys[row * YS_PITCH + c] - mu) * rs * sLnw[c] + sLnb[c];
            ys[row * YS_PITCH + c] = fmaxf(y, 0.f);
        }
    }
    __syncthreads();
#pragma unroll 4
    for (int i = 0; i < 32; i++) {
        int j = i * 256 + tid;
        int row = j >> 6, cp = (j & 63) * 2;
        int node = nodeBase + row;
        if (node < n) {
            float v0 = ys[row * YS_PITCH + cp];
            float v1 = ys[row * YS_PITCH + cp + 1];
            if (out) *(float2*)(out + (size_t)node * C + cp) = make_float2(v0, v1);
            if (outf) {
                __half2 hv = __floats2half2_rn(v0, v1);
                *(__half2*)(outf + (size_t)node * C + cp) = hv;
            }
        }
    }
}

#define SMEM3 (8 * TILE_B + 1536)   // 6 A chunks + 2 W buffers + ctrl = 149 KB
#define SMEM2 (6 * TILE_B + 1536)   // 4 A chunks + 2 W buffers + ctrl = 112 KB

// ---------------- host launch ----------------
extern "C" void kernel_launch(void* const* d_in, const int* in_sizes, int n_in,
                              void* d_out, int out_size) {
    const float* x_user = (const float*)d_in[0];
    const float* x_item = (const float*)d_in[1];
    const int* E0 = (const int*)d_in[2];
    const int* E1 = (const int*)d_in[3];
    const int* E2 = (const int*)d_in[4];

    int *deg, *rowptr, *cursor, *srcs, *bsum, *bofs;
    float *bv;
    __half *x0f, *x1f, *wuf, *wif;
    cudaGetSymbolAddress((void**)&deg, g_deg);
    cudaGetSymbolAddress((void**)&rowptr, g_rowptr);
    cudaGetSymbolAddress((void**)&cursor, g_cursor);
    cudaGetSymbolAddress((void**)&srcs, g_srcs);
    cudaGetSymbolAddress((void**)&bsum, g_bsum);
    cudaGetSymbolAddress((void**)&bofs, g_bofs);
    cudaGetSymbolAddress((void**)&x0f, g_x0f);
    cudaGetSymbolAddress((void**)&x1f, g_x1f);
    cudaGetSymbolAddress((void**)&bv, g_b);
    cudaGetSymbolAddress((void**)&wuf, g_Wuf);
    cudaGetSymbolAddress((void**)&wif, g_Wif);

    cudaFuncSetAttribute(gemm_fused<3>, cudaFuncAttributeMaxDynamicSharedMemorySize, SMEM3);
    cudaFuncSetAttribute(gemm_fused<2>, cudaFuncAttributeMaxDynamicSharedMemorySize, SMEM2);

    const size_t NC = (size_t)NN * C;
    const int* RP[3] = {rowptr, rowptr + (NN + 1), rowptr + 2 * (NN + 1)};
    const int* SS[3] = {srcs, srcs + NE, srcs + 2 * NE};

    cudaStream_t s2;
    cudaStreamCreateWithFlags(&s2, cudaStreamNonBlocking);
    cudaEvent_t ev0, evCSR, evPrep, evU0, evI0, evI1;
    cudaEventCreateWithFlags(&ev0, cudaEventDisableTiming);
    cudaEventCreateWithFlags(&evCSR, cudaEventDisableTiming);
    cudaEventCreateWithFlags(&evPrep, cudaEventDisableTiming);
    cudaEventCreateWithFlags(&evU0, cudaEventDisableTiming);
    cudaEventCreateWithFlags(&evI0, cudaEventDisableTiming);
    cudaEventCreateWithFlags(&evI1, cudaEventDisableTiming);

    const float* lnw[2][2]; const float* lnb[2][2];
    for (int L = 0; L < 2; L++) {
        int pb = 5 + L * 13;
        lnw[L][0] = (const float*)d_in[pb + 9];  lnb[L][0] = (const float*)d_in[pb + 10];
        lnw[L][1] = (const float*)d_in[pb + 11]; lnb[L][1] = (const float*)d_in[pb + 12];
    }

    // fork s2 from main at start
    cudaEventRecord(ev0, 0);
    cudaStreamWaitEvent(s2, ev0, 0);

    // ---- s2: input fp16 conversion + weight prep ----
    split_x<<<dim3(512, 2), 256, 0, s2>>>(x_user, x_item, x0f);
    for (int L = 0; L < 2; L++) {
        int pb = 5 + L * 13;
        prep_user<<<(C * 384 + 255) / 256, 256, 0, s2>>>(
            (const float*)d_in[pb + 3], (const float*)d_in[pb + 4], (const float*)d_in[pb + 5],
            (const float*)d_in[pb + 6], (const float*)d_in[pb + 7], (const float*)d_in[pb + 8],
            wuf + (size_t)L * C * 384, bv + L * 2 * C);
        prep_item<<<(C * 256 + 255) / 256, 256, 0, s2>>>(
            (const float*)d_in[pb + 0], (const float*)d_in[pb + 1], (const float*)d_in[pb + 2],
            wif + (size_t)L * C * 256, bv + L * 2 * C + C);
    }
    cudaEventRecord(evPrep, s2);

    // ---- main: CSR build ----
    cudaMemsetAsync(deg, 0, 3 * NN * sizeof(int), 0);
    histo3<<<dim3(512, 3), 256>>>(E0, E1, E2, deg);
    scan_partial<<<dim3(NB, 3), 256>>>(deg, bsum);
    scan_bsum<<<1, 96>>>(bsum, bofs);
    scan_final<<<dim3(NB, 3), 256>>>(deg, bofs, rowptr, cursor);
    fillcsr3<<<dim3(512, 3), 256>>>(E0, E1, E2, cursor, srcs);
    cudaEventRecord(evCSR, 0);

    const int GG = (NN + 127) / 128;

    // ---- main: user L0 (agg iu from item feats, agg uu from user feats, direct user) ----
    cudaStreamWaitEvent(0, evPrep, 0);
    gemm_fused<3><<<GG, 256, SMEM3>>>(x0f + NC, RP[1], SS[1],
                                      x0f,      RP[2], SS[2],
                                      x0f, wuf, bv, lnw[0][0], lnb[0][0],
                                      nullptr, x1f, NN);
    cudaEventRecord(evU0, 0);

    // ---- s2: item L0 (agg ui from user feats, direct item) ----
    cudaStreamWaitEvent(s2, evCSR, 0);
    gemm_fused<2><<<GG, 256, SMEM2, s2>>>(x0f, RP[0], SS[0],
                                          nullptr, nullptr, nullptr,
                                          x0f + NC, wif, bv + C, lnw[0][1], lnb[0][1],
                                          nullptr, x1f + NC, NN);
    cudaEventRecord(evI0, s2);

    // ---- s2: item L1 (agg ui from x1f user -> needs U0; direct x1f item) ----
    cudaStreamWaitEvent(s2, evU0, 0);
    gemm_fused<2><<<GG, 256, SMEM2, s2>>>(x1f, RP[0], SS[0],
                                          nullptr, nullptr, nullptr,
                                          x1f + NC, wif + (size_t)C * 256, bv + 2 * C + C,
                                          lnw[1][1], lnb[1][1],
                                          (float*)d_out + NC, nullptr, NN);
    cudaEventRecord(evI1, s2);

    // ---- main: user L1 (agg iu from x1f item -> needs I0; agg uu + direct from x1f user) ----
    cudaStreamWaitEvent(0, evI0, 0);
    gemm_fused<3><<<GG, 256, SMEM3>>>(x1f + NC, RP[1], SS[1],
                                      x1f,      RP[2], SS[2],
                                      x1f, wuf + (size_t)C * 384, bv + 2 * C,
                                      lnw[1][0], lnb[1][0],
                                      (float*)d_out, nullptr, NN);
    cudaStreamWaitEvent(0, evI1, 0);
}

// round 10
// speedup vs baseline: 2.2853x; 2.2853x over previous
#include <cuda_runtime.h>
#include <cuda_fp16.h>
#include <cstdint>

#define C   128
#define NN  50000
#define NE  600000
#define NB  49          // ceil(NN/1024)
#define NODES_PER_BLK 64
#define AGG_BLKS ((NN + NODES_PER_BLK - 1) / NODES_PER_BLK)

// ---------------- device scratch (no allocations allowed) ----------------
__device__ __align__(16) __half g_x0f[2 * NN * C];        // fp16 layer-0 inputs
__device__ __align__(16) __half g_x1f[2 * NN * C];        // fp16 layer-0 outputs
__device__ __align__(16) __half g_aggf[2][3 * NN * C];    // [layer][type]: 0 ui, 1 iu, 2 uu
__device__ __align__(16) __half g_Wuf[2][C * 384];
__device__ __align__(16) __half g_Wif[2][C * 256];
__device__ float g_b[2][2 * C];
__device__ int   g_deg[3 * NN];
__device__ int   g_rowptr[3 * (NN + 1)];
__device__ int   g_cursor[3 * NN];
__device__ int   g_srcs[3 * NE];
__device__ int   g_bsum[3 * 64];

// ---------------- fp16 conversion of inputs (+ zeroing deg for the CSR build) ----------------
__global__ void split_x(const float* __restrict__ xu, const float* __restrict__ xi,
                        __half* __restrict__ xf, int* __restrict__ deg) {
    const size_t NC = (size_t)NN * C;
    int y = blockIdx.y;
    // y==0 blocks also zero the degree array (completes before histo3: same stream)
    if (y == 0) {
        for (int i = blockIdx.x * blockDim.x + threadIdx.x; i < 3 * NN; i += gridDim.x * blockDim.x)
            deg[i] = 0;
    }
    const float* x = y ? xi : xu;
    __half* of = xf + y * NC;
    int n4 = NC / 4;
    for (int i = blockIdx.x * blockDim.x + threadIdx.x; i < n4; i += gridDim.x * blockDim.x) {
        float4 v = ((const float4*)x)[i];
        __half2 f0 = __floats2half2_rn(v.x, v.y);
        __half2 f1 = __floats2half2_rn(v.z, v.w);
        uint2 fp; fp.x = *(uint32_t*)&f0; fp.y = *(uint32_t*)&f1;
        ((uint2*)of)[i] = fp;
    }
}

// ---------------- CSR build ----------------
__global__ void histo3(const int* __restrict__ e0, const int* __restrict__ e1, const int* __restrict__ e2,
                       int* __restrict__ deg) {
    int z = blockIdx.y;
    const int* dst = (z == 0 ? e0 : (z == 1 ? e1 : e2)) + NE;
    int* dg = deg + z * NN;
    for (int i = blockIdx.x * blockDim.x + threadIdx.x; i < NE; i += gridDim.x * blockDim.x)
        atomicAdd(&dg[dst[i]], 1);
}

__global__ void scan_partial(const int* __restrict__ deg, int* __restrict__ bsum) {
    int z = blockIdx.y, b = blockIdx.x, t = threadIdx.x;
    int lane = t & 31, wid = t >> 5;
    int s = 0;
#pragma unroll
    for (int q = 0; q < 4; q++) {
        int i = b * 1024 + q * 256 + t;
        if (i < NN) s += deg[z * NN + i];
    }
    for (int o = 16; o; o >>= 1) s += __shfl_down_sync(0xffffffffu, s, o);
    __shared__ int ws[8];
    if (lane == 0) ws[wid] = s;
    __syncthreads();
    if (t == 0) {
        int tot = 0;
#pragma unroll
        for (int w = 0; w < 8; w++) tot += ws[w];
        bsum[z * 64 + b] = tot;
    }
}

// block-local scan + inline scan of the (tiny) per-block sums
__global__ void scan_final(const int* __restrict__ deg, const int* __restrict__ bsum,
                           int* __restrict__ rowptr, int* __restrict__ cursor) {
    int z = blockIdx.y, b = blockIdx.x, t = threadIdx.x;
    int lane = t & 31, wid = t >> 5;
    __shared__ int sb[64];
    __shared__ int ws[8];
    __shared__ int sOfs;
    if (t < 64) sb[t] = (t < NB) ? bsum[z * 64 + t] : 0;

    int base = b * 1024 + t * 4;
    int v[4]; int tsum = 0;
#pragma unroll
    for (int q = 0; q < 4; q++) {
        int i = base + q;
        v[q] = (i < NN) ? deg[z * NN + i] : 0;
        tsum += v[q];
    }
    int incl = tsum;
    for (int o = 1; o < 32; o <<= 1) {
        int x = __shfl_up_sync(0xffffffffu, incl, o);
        if (lane >= o) incl += x;
    }
    if (lane == 31) ws[wid] = incl;
    __syncthreads();
    if (t == 0) {
        int run = 0;
        for (int i = 0; i < b; i++) run += sb[i];
        sOfs = run;
    }
    __syncthreads();
    int wofs = 0;
#pragma unroll
    for (int w = 0; w < 8; w++) wofs += (w < wid) ? ws[w] : 0;
    int run = sOfs + wofs + incl - tsum;
#pragma unroll
    for (int q = 0; q < 4; q++) {
        int i = base + q;
        if (i < NN) {
            rowptr[z * (NN + 1) + i] = run;
            cursor[z * NN + i] = run;
            if (i == NN - 1) rowptr[z * (NN + 1) + NN] = run + v[q];
            run += v[q];
        }
    }
}

__global__ void fillcsr3(const int* __restrict__ e0, const int* __restrict__ e1, const int* __restrict__ e2,
                         int* __restrict__ cursor, int* __restrict__ srcs) {
    int z = blockIdx.y;
    const int* base = (z == 0 ? e0 : (z == 1 ? e1 : e2));
    const int* src = base;
    const int* dst = base + NE;
    int* cur = cursor + z * NN;
    int* out = srcs + z * NE;
    for (int i = blockIdx.x * blockDim.x + threadIdx.x; i < NE; i += gridDim.x * blockDim.x) {
        int p = atomicAdd(&cur[dst[i]], 1);
        out[p] = src[i];
    }
}

// ---------------- mean aggregation: block-dynamic node fetch ----------------
__device__ __forceinline__ void add8(float* acc, uint4 v) {
    __half2* p = (__half2*)&v;
#pragma unroll
    for (int i = 0; i < 4; i++) {
        float2 f = __half22float2(p[i]);
        acc[2 * i] += f.x;
        acc[2 * i + 1] += f.y;
    }
}

// One warp processes one node; lanes split into 2 halves of 16, each half
// streams one edge per step (16 lanes x 8 halves = full 256B row).
__device__ __forceinline__ void agg_node(const __half* __restrict__ xsrc,
                                         const int* __restrict__ rp, const int* __restrict__ ss,
                                         __half* __restrict__ of, int w, int half, int q) {
    int beg = rp[w], end = rp[w + 1];
    float acc[8];
#pragma unroll
    for (int i = 0; i < 8; i++) acc[i] = 0.f;

    int e = beg;
    for (; e + 8 <= end; e += 8) {
        int s0 = ss[e + half];
        int s1 = ss[e + 2 + half];
        int s2 = ss[e + 4 + half];
        int s3 = ss[e + 6 + half];
        uint4 v0 = *(const uint4*)(xsrc + (size_t)s0 * C + q * 8);
        uint4 v1 = *(const uint4*)(xsrc + (size_t)s1 * C + q * 8);
        uint4 v2 = *(const uint4*)(xsrc + (size_t)s2 * C + q * 8);
        uint4 v3 = *(const uint4*)(xsrc + (size_t)s3 * C + q * 8);
        add8(acc, v0); add8(acc, v1); add8(acc, v2); add8(acc, v3);
    }
    for (; e + 2 <= end; e += 2) {
        int s = ss[e + half];
        uint4 v = *(const uint4*)(xsrc + (size_t)s * C + q * 8);
        add8(acc, v);
    }
    if (e < end && half == 0) {
        int s = ss[e];
        uint4 v = *(const uint4*)(xsrc + (size_t)s * C + q * 8);
        add8(acc, v);
    }
#pragma unroll
    for (int i = 0; i < 8; i++) acc[i] += __shfl_xor_sync(0xffffffffu, acc[i], 16);

    if (half == 0) {
        int d = end - beg;
        float inv = 1.0f / (float)(d > 1 ? d : 1);
        __half2 h0 = __floats2half2_rn(acc[0] * inv, acc[1] * inv);
        __half2 h1 = __floats2half2_rn(acc[2] * inv, acc[3] * inv);
        __half2 h2 = __floats2half2_rn(acc[4] * inv, acc[5] * inv);
        __half2 h3 = __floats2half2_rn(acc[6] * inv, acc[7] * inv);
        uint4 o;
        o.x = *(uint32_t*)&h0; o.y = *(uint32_t*)&h1;
        o.z = *(uint32_t*)&h2; o.w = *(uint32_t*)&h3;
        *(uint4*)(of + (size_t)w * C + q * 8) = o;
    }
}

// single edge-type launch
__global__ void __launch_bounds__(256)
agg_t(const __half* __restrict__ xsrc, const int* __restrict__ rp,
      const int* __restrict__ ss, __half* __restrict__ of) {
    __shared__ int sctr;
    if (threadIdx.x == 0) sctr = 0;
    __syncthreads();
    int lane = threadIdx.x & 31;
    int half = lane >> 4, q = lane & 15;
    int base = blockIdx.x * NODES_PER_BLK;
    for (;;) {
        int i;
        if (lane == 0) i = atomicAdd(&sctr, 1);
        i = __shfl_sync(0xffffffffu, i, 0);
        if (i >= NODES_PER_BLK) break;
        int w = base + i;
        if (w >= NN) break;
        agg_node(xsrc, rp, ss, of, w, half, q);
    }
}

// paired edge-type launch (grid.y selects)
__global__ void __launch_bounds__(256)
agg_pair(const __half* __restrict__ s0, const int* __restrict__ rp0, const int* __restrict__ ss0, __half* __restrict__ o0,
         const __half* __restrict__ s1, const int* __restrict__ rp1, const int* __restrict__ ss1, __half* __restrict__ o1) {
    __shared__ int sctr;
    if (threadIdx.x == 0) sctr = 0;
    __syncthreads();
    int z = blockIdx.y;
    const __half* xsrc = z ? s1 : s0;
    const int* rp = z ? rp1 : rp0;
    const int* ss = z ? ss1 : ss0;
    __half* of = z ? o1 : o0;
    int lane = threadIdx.x & 31;
    int half = lane >> 4, q = lane & 15;
    int base = blockIdx.x * NODES_PER_BLK;
    for (;;) {
        int i;
        if (lane == 0) i = atomicAdd(&sctr, 1);
        i = __shfl_sync(0xffffffffu, i, 0);
        if (i >= NODES_PER_BLK) break;
        int w = base + i;
        if (w >= NN) break;
        agg_node(xsrc, rp, ss, of, w, half, q);
    }
}

// ---------------- weight prep: concat to fp16 ----------------
__global__ void prep_user(const float* __restrict__ Wl_iu, const float* __restrict__ b_iu, const float* __restrict__ Wr_iu,
                          const float* __restrict__ Wl_uu, const float* __restrict__ b_uu, const float* __restrict__ Wr_uu,
                          __half* __restrict__ Wf, float* __restrict__ bv) {
    int i = blockIdx.x * blockDim.x + threadIdx.x;
    if (i < C * 384) {
        int c = i / 384, k = i - c * 384;
        float v;
        if (k < 128)      v = Wl_iu[c * 128 + k];
        else if (k < 256) v = Wl_uu[c * 128 + k - 128];
        else              v = Wr_iu[c * 128 + k - 256] + Wr_uu[c * 128 + k - 256];
        Wf[i] = __float2half_rn(v);
        if (i < C) bv[i] = b_iu[i] + b_uu[i];
    }
}

__global__ void prep_item(const float* __restrict__ Wl_ui, const float* __restrict__ b_ui, const float* __restrict__ Wr_ui,
                          __half* __restrict__ Wf, float* __restrict__ bv) {
    int i = blockIdx.x * blockDim.x + threadIdx.x;
    if (i < C * 256) {
        int c = i / 256, k = i - c * 256;
        float v = (k < 128) ? Wl_ui[c * 128 + k] : Wr_ui[c * 128 + k - 128];
        Wf[i] = __float2half_rn(v);
        if (i < C) bv[i] = b_ui[i];
    }
}

// ---------------- mma.sync helpers ----------------
__device__ __forceinline__ uint32_t smem_u32(const void* p) {
    uint32_t a;
    asm("{ .reg .u64 t; cvta.to.shared.u64 t, %1; cvt.u32.u64 %0, t; }" : "=r"(a) : "l"(p));
    return a;
}

#define LDM4(r, addr) \
    asm volatile("ldmatrix.sync.aligned.m8n8.x4.shared.b16 {%0,%1,%2,%3}, [%4];" \
        : "=r"((r)[0]), "=r"((r)[1]), "=r"((r)[2]), "=r"((r)[3]) : "r"(addr))

#define MMAF16(d, a, b0, b1) \
    asm volatile("mma.sync.aligned.m16n8k16.row.col.f32.f16.f16.f32 " \
        "{%0,%1,%2,%3},{%4,%5,%6,%7},{%8,%9},{%0,%1,%2,%3};" \
        : "+f"((d)[0]), "+f"((d)[1]), "+f"((d)[2]), "+f"((d)[3]) \
        : "r"((a)[0]), "r"((a)[1]), "r"((a)[2]), "r"((a)[3]), "r"(b0), "r"(b1))

__device__ __forceinline__ void cp16(uint32_t dst, const void* src, bool pred) {
    int sz = pred ? 16 : 0;
    asm volatile("cp.async.cg.shared.global [%0], [%1], 16, %2;" :: "r"(dst), "l"(src), "r"(sz));
}
__device__ __forceinline__ void cp_commit() { asm volatile("cp.async.commit_group;"); }
__device__ __forceinline__ void cp_wait1() { asm volatile("cp.async.wait_group 1;"); }

// ---------------- cp.async double-buffered fp16 HMMA GEMM + bias + LN + ReLU ----------------
#define SA 0
#define SB 18432
#define BUF_STRIDE 36864
#define CTRL_OFF 73728
#define YS_PITCH 136
#define SMEM_BYTES (73728 + 1536)

template <int NCH>
__global__ void __launch_bounds__(256, 2)
gemm_mma(const __half* __restrict__ A0, const __half* __restrict__ A1, const __half* __restrict__ A2,
         const __half* __restrict__ Wf,
         const float* __restrict__ bias, const float* __restrict__ lnw, const float* __restrict__ lnb,
         float* __restrict__ out, __half* __restrict__ outf, int n) {
    extern __shared__ __align__(16) char smp[];
    const int KTOT = NCH * 128;
    const int NC2 = NCH * 2;
    uint32_t sbase = smem_u32(smp);

    int tid = threadIdx.x, lane = tid & 31, wid = tid >> 5;
    int wr = wid >> 1, wc = wid & 1;
    int nodeBase = blockIdx.x * 128;

    float* sBias = (float*)(smp + CTRL_OFF);
    float* sLnw  = (float*)(smp + CTRL_OFF + 512);
    float* sLnb  = (float*)(smp + CTRL_OFF + 1024);
    if (tid < 128) { sBias[tid] = bias[tid]; sLnw[tid] = lnw[tid]; sLnb[tid] = lnb[tid]; }

    const __half* AS[3] = {A0, A1, A2};

    float D[2][8][4];
#pragma unroll
    for (int a = 0; a < 2; a++)
#pragma unroll
        for (int b = 0; b < 8; b++)
#pragma unroll
            for (int c = 0; c < 4; c++) D[a][b][c] = 0.f;

    auto load_chunk = [&](int c2, int buf) {
        int srcIdx = c2 >> 1;
        int koff = (c2 & 1) * 64;
        const __half* A = AS[srcIdx];
        uint32_t bb = sbase + buf * BUF_STRIDE;
#pragma unroll
        for (int i = 0; i < 4; i++) {
            int j = i * 256 + tid;
            int row = j >> 3, q = j & 7;
            int node = nodeBase + row;
            bool ok = node < n;
            size_t ga = (size_t)(ok ? node : 0) * C + koff + q * 8;
            cp16(bb + SA + row * 144 + q * 16, A + ga, ok);
        }
#pragma unroll
        for (int i = 0; i < 4; i++) {
            int j = i * 256 + tid;
            int row = j >> 3, q = j & 7;
            size_t ga = (size_t)row * KTOT + c2 * 64 + q * 8;
            cp16(bb + SB + row * 144 + q * 16, Wf + ga, true);
        }
    };

    load_chunk(0, 0);
    cp_commit();

#pragma unroll
    for (int c2 = 0; c2 < NC2; c2++) {
        if (c2 + 1 < NC2) load_chunk(c2 + 1, (c2 + 1) & 1);
        cp_commit();
        cp_wait1();
        __syncthreads();
        uint32_t bb = sbase + (c2 & 1) * BUF_STRIDE;
#pragma unroll
        for (int s = 0; s < 4; s++) {
            uint32_t av[2][4], bv4[4][4];
#pragma unroll
            for (int mt = 0; mt < 2; mt++) {
                int row = wr * 32 + mt * 16 + (lane & 15);
                int kb = s * 32 + (lane >> 4) * 16;
                LDM4(av[mt], bb + SA + row * 144 + kb);
            }
#pragma unroll
            for (int bt = 0; bt < 4; bt++) {
                int rown = wc * 64 + bt * 16 + ((lane >> 4) * 8 + (lane & 7));
                int kb = s * 32 + ((lane >> 3) & 1) * 16;
                LDM4(bv4[bt], bb + SB + rown * 144 + kb);
            }
#pragma unroll
            for (int mt = 0; mt < 2; mt++)
#pragma unroll
                for (int bt = 0; bt < 4; bt++) {
                    MMAF16(D[mt][bt * 2],     av[mt], bv4[bt][0], bv4[bt][1]);
                    MMAF16(D[mt][bt * 2 + 1], av[mt], bv4[bt][2], bv4[bt][3]);
                }
        }
        __syncthreads();
    }

    // ---- epilogue: accum + bias -> smem, LN + ReLU, fp32/fp16 stores ----
    float* ys = (float*)smp;
#pragma unroll
    for (int mt = 0; mt < 2; mt++) {
        int r0 = wr * 32 + mt * 16 + (lane >> 2);
#pragma unroll
        for (int bt = 0; bt < 8; bt++) {
            int nn = wc * 64 + bt * 8 + (lane & 3) * 2;
            float b0 = sBias[nn], b1 = sBias[nn + 1];
            float2 v0 = {D[mt][bt][0] + b0, D[mt][bt][1] + b1};
            float2 v1 = {D[mt][bt][2] + b0, D[mt][bt][3] + b1};
            *(float2*)&ys[r0 * YS_PITCH + nn] = v0;
            *(float2*)&ys[(r0 + 8) * YS_PITCH + nn] = v1;
        }
    }
    __syncthreads();
    if (tid < 128) {
        int row = tid;
        float s = 0.f, s2 = 0.f;
#pragma unroll
        for (int c = 0; c < 128; c++) {
            float v = ys[row * YS_PITCH + c];
            s += v; s2 += v * v;
        }
        float mu = s * (1.f / 128.f);
        float rs = rsqrtf(s2 * (1.f / 128.f) - mu * mu + 1e-5f);
#pragma unroll
        for (int c = 0; c < 128; c++) {
            float y = (ys[row * YS_PITCH + c] - mu) * rs * sLnw[c] + sLnb[c];
            ys[row * YS_PITCH + c] = fmaxf(y, 0.f);
        }
    }
    __syncthreads();
#pragma unroll 4
    for (int i = 0; i < 32; i++) {
        int j = i * 256 + tid;
        int row = j >> 6, cp = (j & 63) * 2;
        int node = nodeBase + row;
        if (node < n) {
            float v0 = ys[row * YS_PITCH + cp];
            float v1 = ys[row * YS_PITCH + cp + 1];
            if (out) *(float2*)(out + (size_t)node * C + cp) = make_float2(v0, v1);
            if (outf) {
                __half2 hv = __floats2half2_rn(v0, v1);
                *(__half2*)(outf + (size_t)node * C + cp) = hv;
            }
        }
    }
}

// ---------------- host launch ----------------
extern "C" void kernel_launch(void* const* d_in, const int* in_sizes, int n_in,
                              void* d_out, int out_size) {
    const float* x_user = (const float*)d_in[0];
    const float* x_item = (const float*)d_in[1];
    const int* E0 = (const int*)d_in[2];
    const int* E1 = (const int*)d_in[3];
    const int* E2 = (const int*)d_in[4];

    int *deg, *rowptr, *cursor, *srcs, *bsum;
    float *bv;
    __half *x0f, *x1f, *aggf, *wuf, *wif;
    cudaGetSymbolAddress((void**)&deg, g_deg);
    cudaGetSymbolAddress((void**)&rowptr, g_rowptr);
    cudaGetSymbolAddress((void**)&cursor, g_cursor);
    cudaGetSymbolAddress((void**)&srcs, g_srcs);
    cudaGetSymbolAddress((void**)&bsum, g_bsum);
    cudaGetSymbolAddress((void**)&x0f, g_x0f);
    cudaGetSymbolAddress((void**)&x1f, g_x1f);
    cudaGetSymbolAddress((void**)&aggf, g_aggf);
    cudaGetSymbolAddress((void**)&bv, g_b);
    cudaGetSymbolAddress((void**)&wuf, g_Wuf);
    cudaGetSymbolAddress((void**)&wif, g_Wif);

    cudaFuncSetAttribute(gemm_mma<3>, cudaFuncAttributeMaxDynamicSharedMemorySize, SMEM_BYTES);
    cudaFuncSetAttribute(gemm_mma<2>, cudaFuncAttributeMaxDynamicSharedMemorySize, SMEM_BYTES);

    const size_t NC = (size_t)NN * C;
    __half* Af[2][3];
    for (int L = 0; L < 2; L++)
        for (int t = 0; t < 3; t++)
            Af[L][t] = aggf + (size_t)L * 3 * NC + (size_t)t * NC;
    const int* RP[3] = {rowptr, rowptr + (NN + 1), rowptr + 2 * (NN + 1)};
    const int* SS[3] = {srcs, srcs + NE, srcs + 2 * NE};

    cudaStream_t s2;
    cudaStreamCreateWithFlags(&s2, cudaStreamNonBlocking);
    cudaEvent_t ev0, evCSR, evPrep, evUI1, evIU1, evI1;
    cudaEventCreateWithFlags(&ev0, cudaEventDisableTiming);
    cudaEventCreateWithFlags(&evCSR, cudaEventDisableTiming);
    cudaEventCreateWithFlags(&evPrep, cudaEventDisableTiming);
    cudaEventCreateWithFlags(&evUI1, cudaEventDisableTiming);
    cudaEventCreateWithFlags(&evIU1, cudaEventDisableTiming);
    cudaEventCreateWithFlags(&evI1, cudaEventDisableTiming);

    const float* lnw[2][2]; const float* lnb[2][2];
    for (int L = 0; L < 2; L++) {
        int pb = 5 + L * 13;
        lnw[L][0] = (const float*)d_in[pb + 9];  lnb[L][0] = (const float*)d_in[pb + 10];
        lnw[L][1] = (const float*)d_in[pb + 11]; lnb[L][1] = (const float*)d_in[pb + 12];
    }

    // ---- main: split (zeros deg) + CSR build; kernels 1-5 ----
    split_x<<<dim3(512, 2), 256>>>(x_user, x_item, x0f, deg);            // #1
    histo3<<<dim3(512, 3), 256>>>(E0, E1, E2, deg);                      // #2
    scan_partial<<<dim3(NB, 3), 256>>>(deg, bsum);                       // #3
    scan_final<<<dim3(NB, 3), 256>>>(deg, bsum, rowptr, cursor);         // #4
    fillcsr3<<<dim3(512, 3), 256>>>(E0, E1, E2, cursor, srcs);           // #5
    cudaEventRecord(evCSR, 0);

    // ---- s2: weight prep (concurrent with CSR; only needed before GEMMs) ----
    cudaEventRecord(ev0, 0);  // fork AFTER split submission: s2 preps have no deps on main
    cudaStreamWaitEvent(s2, ev0, 0);
    for (int L = 0; L < 2; L++) {
        int pb = 5 + L * 13;
        prep_user<<<(C * 384 + 255) / 256, 256, 0, s2>>>(
            (const float*)d_in[pb + 3], (const float*)d_in[pb + 4], (const float*)d_in[pb + 5],
            (const float*)d_in[pb + 6], (const float*)d_in[pb + 7], (const float*)d_in[pb + 8],
            wuf + (size_t)L * C * 384, bv + L * 2 * C);
        prep_item<<<(C * 256 + 255) / 256, 256, 0, s2>>>(
            (const float*)d_in[pb + 0], (const float*)d_in[pb + 1], (const float*)d_in[pb + 2],
            wif + (size_t)L * C * 256, bv + L * 2 * C + C);
    }
    cudaEventRecord(evPrep, s2);

    const int GG = (NN + 127) / 128;

    // ======== user pipeline (main) / item pipeline (s2) ========
    agg_pair<<<dim3(AGG_BLKS, 2), 256>>>(x0f + NC, RP[1], SS[1], Af[0][1],   // iu   (kernel #6 on main)
                                         x0f,      RP[2], SS[2], Af[0][2]);  // uu
    cudaStreamWaitEvent(0, evPrep, 0);
    gemm_mma<3><<<GG, 256, SMEM_BYTES>>>(Af[0][1], Af[0][2], x0f,
                                         wuf, bv, lnw[0][0], lnb[0][0],
                                         nullptr, x1f, NN);
    agg_pair<<<dim3(AGG_BLKS, 2), 256>>>(x1f, RP[0], SS[0], Af[1][0],        // ui L1
                                         x1f, RP[2], SS[2], Af[1][2]);       // uu L1
    cudaEventRecord(evUI1, 0);

    cudaStreamWaitEvent(s2, evCSR, 0);
    agg_t<<<AGG_BLKS, 256, 0, s2>>>(x0f, RP[0], SS[0], Af[0][0]);            // ui
    gemm_mma<2><<<GG, 256, SMEM_BYTES, s2>>>(Af[0][0], x0f + NC, nullptr,
                                             wif, bv + C, lnw[0][1], lnb[0][1],
                                             nullptr, x1f + NC, NN);
    agg_t<<<AGG_BLKS, 256, 0, s2>>>(x1f + NC, RP[1], SS[1], Af[1][1]);       // iu L1
    cudaEventRecord(evIU1, s2);
    cudaStreamWaitEvent(s2, evUI1, 0);
    gemm_mma<2><<<GG, 256, SMEM_BYTES, s2>>>(Af[1][0], x1f + NC, nullptr,
                                             wif + (size_t)C * 256, bv + 2 * C + C,
                                             lnw[1][1], lnb[1][1],
                                             (float*)d_out + NC, nullptr, NN);
    cudaEventRecord(evI1, s2);

    cudaStreamWaitEvent(0, evIU1, 0);
    gemm_mma<3><<<GG, 256, SMEM_BYTES>>>(Af[1][1], Af[1][2], x1f,
                                         wuf + (size_t)C * 384, bv + 2 * C,
                                         lnw[1][0], lnb[1][0],
                                         (float*)d_out, nullptr, NN);
    cudaStreamWaitEvent(0, evI1, 0);
}

// round 11
// speedup vs baseline: 2.2982x; 1.0057x over previous
#include <cuda_runtime.h>
#include <cuda_fp16.h>
#include <cstdint>

#define C   128
#define NN  50000
#define NE  600000
#define NB  49          // ceil(NN/1024)
#define NODES_PER_BLK 64
#define AGG_BLKS ((NN + NODES_PER_BLK - 1) / NODES_PER_BLK)

// ---------------- device scratch (no allocations allowed) ----------------
__device__ __align__(16) __half g_x0f[2 * NN * C];        // fp16 layer-0 inputs
__device__ __align__(16) __half g_x1f[2 * NN * C];        // fp16 layer-0 outputs
__device__ __align__(16) __half g_aggf[2][3 * NN * C];    // [layer][type]: 0 ui, 1 iu, 2 uu
__device__ __align__(16) __half g_Wuf[2][C * 384];
__device__ __align__(16) __half g_Wif[2][C * 256];
__device__ float g_b[2][2 * C];
__device__ int   g_deg[3 * NN];
__device__ int   g_rowptr[3 * (NN + 1)];
__device__ int   g_cursor[3 * NN];
__device__ int   g_srcs[3 * NE];
__device__ int   g_bsum[3 * 64];

// ---------------- tiny zero kernel (deg) ----------------
__global__ void zero_deg(int* __restrict__ deg) {
    for (int i = blockIdx.x * blockDim.x + threadIdx.x; i < 3 * NN; i += gridDim.x * blockDim.x)
        deg[i] = 0;
}

// ---------------- fp16 conversion of inputs ----------------
__global__ void split_x(const float* __restrict__ xu, const float* __restrict__ xi,
                        __half* __restrict__ xf) {
    const size_t NC = (size_t)NN * C;
    int y = blockIdx.y;
    const float* x = y ? xi : xu;
    __half* of = xf + y * NC;
    int n4 = NC / 4;
    for (int i = blockIdx.x * blockDim.x + threadIdx.x; i < n4; i += gridDim.x * blockDim.x) {
        float4 v = ((const float4*)x)[i];
        __half2 f0 = __floats2half2_rn(v.x, v.y);
        __half2 f1 = __floats2half2_rn(v.z, v.w);
        uint2 fp; fp.x = *(uint32_t*)&f0; fp.y = *(uint32_t*)&f1;
        ((uint2*)of)[i] = fp;
    }
}

// ---------------- CSR build ----------------
__global__ void histo3(const int* __restrict__ e0, const int* __restrict__ e1, const int* __restrict__ e2,
                       int* __restrict__ deg) {
    int z = blockIdx.y;
    const int* dst = (z == 0 ? e0 : (z == 1 ? e1 : e2)) + NE;
    int* dg = deg + z * NN;
    for (int i = blockIdx.x * blockDim.x + threadIdx.x; i < NE; i += gridDim.x * blockDim.x)
        atomicAdd(&dg[dst[i]], 1);
}

__global__ void scan_partial(const int* __restrict__ deg, int* __restrict__ bsum) {
    int z = blockIdx.y, b = blockIdx.x, t = threadIdx.x;
    int lane = t & 31, wid = t >> 5;
    int s = 0;
#pragma unroll
    for (int q = 0; q < 4; q++) {
        int i = b * 1024 + q * 256 + t;
        if (i < NN) s += deg[z * NN + i];
    }
    for (int o = 16; o; o >>= 1) s += __shfl_down_sync(0xffffffffu, s, o);
    __shared__ int ws[8];
    if (lane == 0) ws[wid] = s;
    __syncthreads();
    if (t == 0) {
        int tot = 0;
#pragma unroll
        for (int w = 0; w < 8; w++) tot += ws[w];
        bsum[z * 64 + b] = tot;
    }
}

// block-local scan + inline scan of the (tiny) per-block sums
__global__ void scan_final(const int* __restrict__ deg, const int* __restrict__ bsum,
                           int* __restrict__ rowptr, int* __restrict__ cursor) {
    int z = blockIdx.y, b = blockIdx.x, t = threadIdx.x;
    int lane = t & 31, wid = t >> 5;
    __shared__ int sb[64];
    __shared__ int ws[8];
    __shared__ int sOfs;
    if (t < 64) sb[t] = (t < NB) ? bsum[z * 64 + t] : 0;

    int base = b * 1024 + t * 4;
    int v[4]; int tsum = 0;
#pragma unroll
    for (int q = 0; q < 4; q++) {
        int i = base + q;
        v[q] = (i < NN) ? deg[z * NN + i] : 0;
        tsum += v[q];
    }
    int incl = tsum;
    for (int o = 1; o < 32; o <<= 1) {
        int x = __shfl_up_sync(0xffffffffu, incl, o);
        if (lane >= o) incl += x;
    }
    if (lane == 31) ws[wid] = incl;
    __syncthreads();
    if (t == 0) {
        int run = 0;
        for (int i = 0; i < b; i++) run += sb[i];
        sOfs = run;
    }
    __syncthreads();
    int wofs = 0;
#pragma unroll
    for (int w = 0; w < 8; w++) wofs += (w < wid) ? ws[w] : 0;
    int run = sOfs + wofs + incl - tsum;
#pragma unroll
    for (int q = 0; q < 4; q++) {
        int i = base + q;
        if (i < NN) {
            rowptr[z * (NN + 1) + i] = run;
            cursor[z * NN + i] = run;
            if (i == NN - 1) rowptr[z * (NN + 1) + NN] = run + v[q];
            run += v[q];
        }
    }
}

__global__ void fillcsr3(const int* __restrict__ e0, const int* __restrict__ e1, const int* __restrict__ e2,
                         int* __restrict__ cursor, int* __restrict__ srcs) {
    int z = blockIdx.y;
    const int* base = (z == 0 ? e0 : (z == 1 ? e1 : e2));
    const int* src = base;
    const int* dst = base + NE;
    int* cur = cursor + z * NN;
    int* out = srcs + z * NE;
    for (int i = blockIdx.x * blockDim.x + threadIdx.x; i < NE; i += gridDim.x * blockDim.x) {
        int p = atomicAdd(&cur[dst[i]], 1);
        out[p] = src[i];
    }
}

// ---------------- mean aggregation: block-dynamic node fetch ----------------
__device__ __forceinline__ void add8(float* acc, uint4 v) {
    __half2* p = (__half2*)&v;
#pragma unroll
    for (int i = 0; i < 4; i++) {
        float2 f = __half22float2(p[i]);
        acc[2 * i] += f.x;
        acc[2 * i + 1] += f.y;
    }
}

// One warp processes one node; lanes split into 2 halves of 16, each half
// streams one edge per step (16 lanes x 8 halves = full 256B row).
__device__ __forceinline__ void agg_node(const __half* __restrict__ xsrc,
                                         const int* __restrict__ rp, const int* __restrict__ ss,
                                         __half* __restrict__ of, int w, int half, int q) {
    int beg = rp[w], end = rp[w + 1];
    float acc[8];
#pragma unroll
    for (int i = 0; i < 8; i++) acc[i] = 0.f;

    int e = beg;
    for (; e + 8 <= end; e += 8) {
        int s0 = ss[e + half];
        int s1 = ss[e + 2 + half];
        int s2 = ss[e + 4 + half];
        int s3 = ss[e + 6 + half];
        uint4 v0 = *(const uint4*)(xsrc + (size_t)s0 * C + q * 8);
        uint4 v1 = *(const uint4*)(xsrc + (size_t)s1 * C + q * 8);
        uint4 v2 = *(const uint4*)(xsrc + (size_t)s2 * C + q * 8);
        uint4 v3 = *(const uint4*)(xsrc + (size_t)s3 * C + q * 8);
        add8(acc, v0); add8(acc, v1); add8(acc, v2); add8(acc, v3);
    }
    for (; e + 2 <= end; e += 2) {
        int s = ss[e + half];
        uint4 v = *(const uint4*)(xsrc + (size_t)s * C + q * 8);
        add8(acc, v);
    }
    if (e < end && half == 0) {
        int s = ss[e];
        uint4 v = *(const uint4*)(xsrc + (size_t)s * C + q * 8);
        add8(acc, v);
    }
#pragma unroll
    for (int i = 0; i < 8; i++) acc[i] += __shfl_xor_sync(0xffffffffu, acc[i], 16);

    if (half == 0) {
        int d = end - beg;
        float inv = 1.0f / (float)(d > 1 ? d : 1);
        __half2 h0 = __floats2half2_rn(acc[0] * inv, acc[1] * inv);
        __half2 h1 = __floats2half2_rn(acc[2] * inv, acc[3] * inv);
        __half2 h2 = __floats2half2_rn(acc[4] * inv, acc[5] * inv);
        __half2 h3 = __floats2half2_rn(acc[6] * inv, acc[7] * inv);
        uint4 o;
        o.x = *(uint32_t*)&h0; o.y = *(uint32_t*)&h1;
        o.z = *(uint32_t*)&h2; o.w = *(uint32_t*)&h3;
        *(uint4*)(of + (size_t)w * C + q * 8) = o;
    }
}

// single edge-type launch
__global__ void __launch_bounds__(256)
agg_t(const __half* __restrict__ xsrc, const int* __restrict__ rp,
      const int* __restrict__ ss, __half* __restrict__ of) {
    __shared__ int sctr;
    if (threadIdx.x == 0) sctr = 0;
    __syncthreads();
    int lane = threadIdx.x & 31;
    int half = lane >> 4, q = lane & 15;
    int base = blockIdx.x * NODES_PER_BLK;
    for (;;) {
        int i;
        if (lane == 0) i = atomicAdd(&sctr, 1);
        i = __shfl_sync(0xffffffffu, i, 0);
        if (i >= NODES_PER_BLK) break;
        int w = base + i;
        if (w >= NN) break;
        agg_node(xsrc, rp, ss, of, w, half, q);
    }
}

// paired edge-type launch (grid.y selects)
__global__ void __launch_bounds__(256)
agg_pair(const __half* __restrict__ s0, const int* __restrict__ rp0, const int* __restrict__ ss0, __half* __restrict__ o0,
         const __half* __restrict__ s1, const int* __restrict__ rp1, const int* __restrict__ ss1, __half* __restrict__ o1) {
    __shared__ int sctr;
    if (threadIdx.x == 0) sctr = 0;
    __syncthreads();
    int z = blockIdx.y;
    const __half* xsrc = z ? s1 : s0;
    const int* rp = z ? rp1 : rp0;
    const int* ss = z ? ss1 : ss0;
    __half* of = z ? o1 : o0;
    int lane = threadIdx.x & 31;
    int half = lane >> 4, q = lane & 15;
    int base = blockIdx.x * NODES_PER_BLK;
    for (;;) {
        int i;
        if (lane == 0) i = atomicAdd(&sctr, 1);
        i = __shfl_sync(0xffffffffu, i, 0);
        if (i >= NODES_PER_BLK) break;
        int w = base + i;
        if (w >= NN) break;
        agg_node(xsrc, rp, ss, of, w, half, q);
    }
}

// ---------------- weight prep: concat to fp16 ----------------
__global__ void prep_user(const float* __restrict__ Wl_iu, const float* __restrict__ b_iu, const float* __restrict__ Wr_iu,
                          const float* __restrict__ Wl_uu, const float* __restrict__ b_uu, const float* __restrict__ Wr_uu,
                          __half* __restrict__ Wf, float* __restrict__ bv) {
    int i = blockIdx.x * blockDim.x + threadIdx.x;
    if (i < C * 384) {
        int c = i / 384, k = i - c * 384;
        float v;
        if (k < 128)      v = Wl_iu[c * 128 + k];
        else if (k < 256) v = Wl_uu[c * 128 + k - 128];
        else              v = Wr_iu[c * 128 + k - 256] + Wr_uu[c * 128 + k - 256];
        Wf[i] = __float2half_rn(v);
        if (i < C) bv[i] = b_iu[i] + b_uu[i];
    }
}

__global__ void prep_item(const float* __restrict__ Wl_ui, const float* __restrict__ b_ui, const float* __restrict__ Wr_ui,
                          __half* __restrict__ Wf, float* __restrict__ bv) {
    int i = blockIdx.x * blockDim.x + threadIdx.x;
    if (i < C * 256) {
        int c = i / 256, k = i - c * 256;
        float v = (k < 128) ? Wl_ui[c * 128 + k] : Wr_ui[c * 128 + k - 128];
        Wf[i] = __float2half_rn(v);
        if (i < C) bv[i] = b_ui[i];
    }
}

// ---------------- mma.sync helpers ----------------
__device__ __forceinline__ uint32_t smem_u32(const void* p) {
    uint32_t a;
    asm("{ .reg .u64 t; cvta.to.shared.u64 t, %1; cvt.u32.u64 %0, t; }" : "=r"(a) : "l"(p));
    return a;
}

#define LDM4(r, addr) \
    asm volatile("ldmatrix.sync.aligned.m8n8.x4.shared.b16 {%0,%1,%2,%3}, [%4];" \
        : "=r"((r)[0]), "=r"((r)[1]), "=r"((r)[2]), "=r"((r)[3]) : "r"(addr))

#define MMAF16(d, a, b0, b1) \
    asm volatile("mma.sync.aligned.m16n8k16.row.col.f32.f16.f16.f32 " \
        "{%0,%1,%2,%3},{%4,%5,%6,%7},{%8,%9},{%0,%1,%2,%3};" \
        : "+f"((d)[0]), "+f"((d)[1]), "+f"((d)[2]), "+f"((d)[3]) \
        : "r"((a)[0]), "r"((a)[1]), "r"((a)[2]), "r"((a)[3]), "r"(b0), "r"(b1))

__device__ __forceinline__ void cp16(uint32_t dst, const void* src, bool pred) {
    int sz = pred ? 16 : 0;
    asm volatile("cp.async.cg.shared.global [%0], [%1], 16, %2;" :: "r"(dst), "l"(src), "r"(sz));
}
__device__ __forceinline__ void cp_commit() { asm volatile("cp.async.commit_group;"); }
__device__ __forceinline__ void cp_wait1() { asm volatile("cp.async.wait_group 1;"); }

// ---------------- cp.async double-buffered fp16 HMMA GEMM + bias + LN + ReLU ----------------
#define SA 0
#define SB 18432
#define BUF_STRIDE 36864
#define CTRL_OFF 73728
#define YS_PITCH 136
#define SMEM_BYTES (73728 + 1536)

template <int NCH>
__global__ void __launch_bounds__(256, 2)
gemm_mma(const __half* __restrict__ A0, const __half* __restrict__ A1, const __half* __restrict__ A2,
         const __half* __restrict__ Wf,
         const float* __restrict__ bias, const float* __restrict__ lnw, const float* __restrict__ lnb,
         float* __restrict__ out, __half* __restrict__ outf, int n) {
    extern __shared__ __align__(16) char smp[];
    const int KTOT = NCH * 128;
    const int NC2 = NCH * 2;
    uint32_t sbase = smem_u32(smp);

    int tid = threadIdx.x, lane = tid & 31, wid = tid >> 5;
    int wr = wid >> 1, wc = wid & 1;
    int nodeBase = blockIdx.x * 128;

    float* sBias = (float*)(smp + CTRL_OFF);
    float* sLnw  = (float*)(smp + CTRL_OFF + 512);
    float* sLnb  = (float*)(smp + CTRL_OFF + 1024);
    if (tid < 128) { sBias[tid] = bias[tid]; sLnw[tid] = lnw[tid]; sLnb[tid] = lnb[tid]; }

    const __half* AS[3] = {A0, A1, A2};

    float D[2][8][4];
#pragma unroll
    for (int a = 0; a < 2; a++)
#pragma unroll
        for (int b = 0; b < 8; b++)
#pragma unroll
            for (int c = 0; c < 4; c++) D[a][b][c] = 0.f;

    auto load_chunk = [&](int c2, int buf) {
        int srcIdx = c2 >> 1;
        int koff = (c2 & 1) * 64;
        const __half* A = AS[srcIdx];
        uint32_t bb = sbase + buf * BUF_STRIDE;
#pragma unroll
        for (int i = 0; i < 4; i++) {
            int j = i * 256 + tid;
            int row = j >> 3, q = j & 7;
            int node = nodeBase + row;
            bool ok = node < n;
            size_t ga = (size_t)(ok ? node : 0) * C + koff + q * 8;
            cp16(bb + SA + row * 144 + q * 16, A + ga, ok);
        }
#pragma unroll
        for (int i = 0; i < 4; i++) {
            int j = i * 256 + tid;
            int row = j >> 3, q = j & 7;
            size_t ga = (size_t)row * KTOT + c2 * 64 + q * 8;
            cp16(bb + SB + row * 144 + q * 16, Wf + ga, true);
        }
    };

    load_chunk(0, 0);
    cp_commit();

#pragma unroll
    for (int c2 = 0; c2 < NC2; c2++) {
        if (c2 + 1 < NC2) load_chunk(c2 + 1, (c2 + 1) & 1);
        cp_commit();
        cp_wait1();
        __syncthreads();
        uint32_t bb = sbase + (c2 & 1) * BUF_STRIDE;
#pragma unroll
        for (int s = 0; s < 4; s++) {
            uint32_t av[2][4], bv4[4][4];
#pragma unroll
            for (int mt = 0; mt < 2; mt++) {
                int row = wr * 32 + mt * 16 + (lane & 15);
                int kb = s * 32 + (lane >> 4) * 16;
                LDM4(av[mt], bb + SA + row * 144 + kb);
            }
#pragma unroll
            for (int bt = 0; bt < 4; bt++) {
                int rown = wc * 64 + bt * 16 + ((lane >> 4) * 8 + (lane & 7));
                int kb = s * 32 + ((lane >> 3) & 1) * 16;
                LDM4(bv4[bt], bb + SB + rown * 144 + kb);
            }
#pragma unroll
            for (int mt = 0; mt < 2; mt++)
#pragma unroll
                for (int bt = 0; bt < 4; bt++) {
                    MMAF16(D[mt][bt * 2],     av[mt], bv4[bt][0], bv4[bt][1]);
                    MMAF16(D[mt][bt * 2 + 1], av[mt], bv4[bt][2], bv4[bt][3]);
                }
        }
        __syncthreads();
    }

    // ---- epilogue: accum + bias -> smem, LN + ReLU, fp32/fp16 stores ----
    float* ys = (float*)smp;
#pragma unroll
    for (int mt = 0; mt < 2; mt++) {
        int r0 = wr * 32 + mt * 16 + (lane >> 2);
#pragma unroll
        for (int bt = 0; bt < 8; bt++) {
            int nn = wc * 64 + bt * 8 + (lane & 3) * 2;
            float b0 = sBias[nn], b1 = sBias[nn + 1];
            float2 v0 = {D[mt][bt][0] + b0, D[mt][bt][1] + b1};
            float2 v1 = {D[mt][bt][2] + b0, D[mt][bt][3] + b1};
            *(float2*)&ys[r0 * YS_PITCH + nn] = v0;
            *(float2*)&ys[(r0 + 8) * YS_PITCH + nn] = v1;
        }
    }
    __syncthreads();
    if (tid < 128) {
        int row = tid;
        float s = 0.f, s2 = 0.f;
#pragma unroll
        for (int c = 0; c < 128; c++) {
            float v = ys[row * YS_PITCH + c];
            s += v; s2 += v * v;
        }
        float mu = s * (1.f / 128.f);
        float rs = rsqrtf(s2 * (1.f / 128.f) - mu * mu + 1e-5f);
#pragma unroll
        for (int c = 0; c < 128; c++) {
            float y = (ys[row * YS_PITCH + c] - mu) * rs * sLnw[c] + sLnb[c];
            ys[row * YS_PITCH + c] = fmaxf(y, 0.f);
        }
    }
    __syncthreads();
#pragma unroll 4
    for (int i = 0; i < 32; i++) {
        int j = i * 256 + tid;
        int row = j >> 6, cp = (j & 63) * 2;
        int node = nodeBase + row;
        if (node < n) {
            float v0 = ys[row * YS_PITCH + cp];
            float v1 = ys[row * YS_PITCH + cp + 1];
            if (out) *(float2*)(out + (size_t)node * C + cp) = make_float2(v0, v1);
            if (outf) {
                __half2 hv = __floats2half2_rn(v0, v1);
                *(__half2*)(outf + (size_t)node * C + cp) = hv;
            }
        }
    }
}

// ---------------- host launch ----------------
extern "C" void kernel_launch(void* const* d_in, const int* in_sizes, int n_in,
                              void* d_out, int out_size) {
    const float* x_user = (const float*)d_in[0];
    const float* x_item = (const float*)d_in[1];
    const int* E0 = (const int*)d_in[2];
    const int* E1 = (const int*)d_in[3];
    const int* E2 = (const int*)d_in[4];

    int *deg, *rowptr, *cursor, *srcs, *bsum;
    float *bv;
    __half *x0f, *x1f, *aggf, *wuf, *wif;
    cudaGetSymbolAddress((void**)&deg, g_deg);
    cudaGetSymbolAddress((void**)&rowptr, g_rowptr);
    cudaGetSymbolAddress((void**)&cursor, g_cursor);
    cudaGetSymbolAddress((void**)&srcs, g_srcs);
    cudaGetSymbolAddress((void**)&bsum, g_bsum);
    cudaGetSymbolAddress((void**)&x0f, g_x0f);
    cudaGetSymbolAddress((void**)&x1f, g_x1f);
    cudaGetSymbolAddress((void**)&aggf, g_aggf);
    cudaGetSymbolAddress((void**)&bv, g_b);
    cudaGetSymbolAddress((void**)&wuf, g_Wuf);
    cudaGetSymbolAddress((void**)&wif, g_Wif);

    cudaFuncSetAttribute(gemm_mma<3>, cudaFuncAttributeMaxDynamicSharedMemorySize, SMEM_BYTES);
    cudaFuncSetAttribute(gemm_mma<2>, cudaFuncAttributeMaxDynamicSharedMemorySize, SMEM_BYTES);

    const size_t NC = (size_t)NN * C;
    __half* Af[2][3];
    for (int L = 0; L < 2; L++)
        for (int t = 0; t < 3; t++)
            Af[L][t] = aggf + (size_t)L * 3 * NC + (size_t)t * NC;
    const int* RP[3] = {rowptr, rowptr + (NN + 1), rowptr + 2 * (NN + 1)};
    const int* SS[3] = {srcs, srcs + NE, srcs + 2 * NE};

    cudaStream_t s2;
    cudaStreamCreateWithFlags(&s2, cudaStreamNonBlocking);
    cudaEvent_t ev0, evCSR, evPrep, evUI1, evIU1, evI1;
    cudaEventCreateWithFlags(&ev0, cudaEventDisableTiming);
    cudaEventCreateWithFlags(&evCSR, cudaEventDisableTiming);
    cudaEventCreateWithFlags(&evPrep, cudaEventDisableTiming);
    cudaEventCreateWithFlags(&evUI1, cudaEventDisableTiming);
    cudaEventCreateWithFlags(&evIU1, cudaEventDisableTiming);
    cudaEventCreateWithFlags(&evI1, cudaEventDisableTiming);

    const float* lnw[2][2]; const float* lnb[2][2];
    for (int L = 0; L < 2; L++) {
        int pb = 5 + L * 13;
        lnw[L][0] = (const float*)d_in[pb + 9];  lnb[L][0] = (const float*)d_in[pb + 10];
        lnw[L][1] = (const float*)d_in[pb + 11]; lnb[L][1] = (const float*)d_in[pb + 12];
    }

    // fork s2 at start
    cudaEventRecord(ev0, 0);
    cudaStreamWaitEvent(s2, ev0, 0);

    // ---- s2: fp16 split + weight prep (shadowed by main's CSR build) ----
    split_x<<<dim3(512, 2), 256, 0, s2>>>(x_user, x_item, x0f);
    for (int L = 0; L < 2; L++) {
        int pb = 5 + L * 13;
        prep_user<<<(C * 384 + 255) / 256, 256, 0, s2>>>(
            (const float*)d_in[pb + 3], (const float*)d_in[pb + 4], (const float*)d_in[pb + 5],
            (const float*)d_in[pb + 6], (const float*)d_in[pb + 7], (const float*)d_in[pb + 8],
            wuf + (size_t)L * C * 384, bv + L * 2 * C);
        prep_item<<<(C * 256 + 255) / 256, 256, 0, s2>>>(
            (const float*)d_in[pb + 0], (const float*)d_in[pb + 1], (const float*)d_in[pb + 2],
            wif + (size_t)L * C * 256, bv + L * 2 * C + C);
    }
    cudaEventRecord(evPrep, s2);

    // ---- main: CSR build ----
    zero_deg<<<128, 256>>>(deg);
    histo3<<<dim3(512, 3), 256>>>(E0, E1, E2, deg);
    scan_partial<<<dim3(NB, 3), 256>>>(deg, bsum);
    scan_final<<<dim3(NB, 3), 256>>>(deg, bsum, rowptr, cursor);
    fillcsr3<<<dim3(512, 3), 256>>>(E0, E1, E2, cursor, srcs);
    cudaEventRecord(evCSR, 0);

    const int GG = (NN + 127) / 128;

    // ======== user pipeline (main) / item pipeline (s2) ========
    cudaStreamWaitEvent(0, evPrep, 0);
    agg_pair<<<dim3(AGG_BLKS, 2), 256>>>(x0f + NC, RP[1], SS[1], Af[0][1],   // iu
                                         x0f,      RP[2], SS[2], Af[0][2]);  // uu
    gemm_mma<3><<<GG, 256, SMEM_BYTES>>>(Af[0][1], Af[0][2], x0f,
                                         wuf, bv, lnw[0][0], lnb[0][0],
                                         nullptr, x1f, NN);
    agg_t<<<AGG_BLKS, 256>>>(x1f, RP[0], SS[0], Af[1][0]);                   // ui L1 (gates item GEMM L1)
    cudaEventRecord(evUI1, 0);
    agg_t<<<AGG_BLKS, 256>>>(x1f, RP[2], SS[2], Af[1][2]);                   // uu L1

    cudaStreamWaitEvent(s2, evCSR, 0);
    agg_t<<<AGG_BLKS, 256, 0, s2>>>(x0f, RP[0], SS[0], Af[0][0]);            // ui
    gemm_mma<2><<<GG, 256, SMEM_BYTES, s2>>>(Af[0][0], x0f + NC, nullptr,
                                             wif, bv + C, lnw[0][1], lnb[0][1],
                                             nullptr, x1f + NC, NN);
    agg_t<<<AGG_BLKS, 256, 0, s2>>>(x1f + NC, RP[1], SS[1], Af[1][1]);       // iu L1
    cudaEventRecord(evIU1, s2);
    cudaStreamWaitEvent(s2, evUI1, 0);
    gemm_mma<2><<<GG, 256, SMEM_BYTES, s2>>>(Af[1][0], x1f + NC, nullptr,
                                             wif + (size_t)C * 256, bv + 2 * C + C,
                                             lnw[1][1], lnb[1][1],
                                             (float*)d_out + NC, nullptr, NN);
    cudaEventRecord(evI1, s2);

    cudaStreamWaitEvent(0, evIU1, 0);
    gemm_mma<3><<<GG, 256, SMEM_BYTES>>>(Af[1][1], Af[1][2], x1f,
                                         wuf + (size_t)C * 384, bv + 2 * C,
                                         lnw[1][0], lnb[1][0],
                                         (float*)d_out, nullptr, NN);
    cudaStreamWaitEvent(0, evI1, 0);
}